// round 8
// baseline (speedup 1.0000x reference)
#include <cuda_runtime.h>
#include <cuda_bf16.h>
#include <cstdint>

// ===================== problem constants =====================
#define B_SZ   4
#define T_SZ   256
#define U_SZ   128
#define EH_SZ  512
#define PH_SZ  320
#define JH_SZ  512
#define NC_SZ  1025
#define NPAD   1152           // 9 * 128
#define NTILES 9

// ===================== device scratch (statically declared; no allocs) =====================
__device__ float          g_e[B_SZ * T_SZ * JH_SZ];   // [B*T, JH] fp32 (2 MB)
__device__ float          g_p[B_SZ * U_SZ * JH_SZ];   // [B*U, JH] fp32 (1 MB)
__device__ __nv_bfloat16  g_WT[NPAD * JH_SZ];         // W_out^T bf16 [NPAD, JH] (1.18 MB)
__device__ float          g_bias[NPAD];               // b_out padded with 0

__device__ __forceinline__ uint32_t smem_to_u32(const void* smem_ptr) {
    uint32_t addr;
    asm("{ .reg .u64 tmp; cvta.to.shared.u64 tmp, %1; cvt.u32.u64 %0, tmp; }"
        : "=r"(addr) : "l"(smem_ptr));
    return addr;
}

// ===================== projection GEMM: out[b*R + r, j] = sum_h X[b,h,r]*W[h,j] + bias[j] =====================
__global__ void __launch_bounds__(256) proj_kernel(
    const float* __restrict__ X, const float* __restrict__ W,
    const float* __restrict__ bias, int which, int K, int R)
{
    float* out = which ? g_p : g_e;
    __shared__ float As[32][64];
    __shared__ float Bs[32][64];

    const int tid = threadIdx.x;
    const int tx = tid & 15, ty = tid >> 4;
    const int r0 = blockIdx.x * 64;
    const int j0 = blockIdx.y * 64;
    const int b  = r0 / R;
    const int t0 = r0 % R;
    const float* Xb = X + (size_t)b * K * R;

    float acc[4][4];
    #pragma unroll
    for (int i = 0; i < 4; ++i)
        #pragma unroll
        for (int j = 0; j < 4; ++j) acc[i][j] = 0.f;

    for (int k0 = 0; k0 < K; k0 += 32) {
        #pragma unroll
        for (int i = 0; i < 8; ++i) {
            int idx = tid + i * 256;
            int kk = idx >> 6, tt = idx & 63;
            As[kk][tt] = Xb[(size_t)(k0 + kk) * R + t0 + tt];
        }
        #pragma unroll
        for (int i = 0; i < 8; ++i) {
            int idx = tid + i * 256;
            int kk = idx >> 6, jj = idx & 63;
            Bs[kk][jj] = W[(size_t)(k0 + kk) * JH_SZ + j0 + jj];
        }
        __syncthreads();
        #pragma unroll
        for (int kk = 0; kk < 32; ++kk) {
            float a[4], bb[4];
            #pragma unroll
            for (int i = 0; i < 4; ++i) a[i]  = As[kk][ty * 4 + i];
            #pragma unroll
            for (int j = 0; j < 4; ++j) bb[j] = Bs[kk][tx * 4 + j];
            #pragma unroll
            for (int i = 0; i < 4; ++i)
                #pragma unroll
                for (int j = 0; j < 4; ++j) acc[i][j] += a[i] * bb[j];
        }
        __syncthreads();
    }

    #pragma unroll
    for (int i = 0; i < 4; ++i)
        #pragma unroll
        for (int j = 0; j < 4; ++j) {
            int jj = j0 + tx * 4 + j;
            out[(size_t)(r0 + ty * 4 + i) * JH_SZ + jj] = acc[i][j] + bias[jj];
        }
}

// ===================== W_out transpose + pad: g_WT[n,j] = bf16(W_out[j,n]); g_bias pad =====================
__global__ void prep_wt_kernel(const float* __restrict__ W_out, const float* __restrict__ b_out)
{
    __shared__ float tile[32][33];
    const int tx = threadIdx.x, ty = threadIdx.y;
    const int n0 = blockIdx.x * 32;     // 36 blocks -> 1152
    const int j0 = blockIdx.y * 32;     // 16 blocks -> 512

    #pragma unroll
    for (int k = 0; k < 4; ++k) {
        int j = j0 + ty + k * 8;
        int n = n0 + tx;
        tile[ty + k * 8][tx] = (n < NC_SZ) ? W_out[(size_t)j * NC_SZ + n] : 0.f;
    }
    __syncthreads();
    #pragma unroll
    for (int k = 0; k < 4; ++k) {
        int n = n0 + ty + k * 8;
        int j = j0 + tx;
        g_WT[(size_t)n * JH_SZ + j] = __float2bfloat16(tile[tx][ty + k * 8]);
    }
    if (blockIdx.y == 0 && ty == 0) {
        int n = n0 + tx;
        g_bias[n] = (n < NC_SZ) ? b_out[n] : 0.f;
    }
}

// ===================== joint kernel (mma.sync bf16) =====================
// CTA = one (b,t): M=128 rows (all u). A[u,j] = bf16(relu(e[b,t,j]+p[b,u,j])) in smem.
// Loop 9 N-tiles of 128; B chunks [128n x 128k] cp.async double-buffered.
// Warps: 4M x 2N -> each warp 32 rows x 64 cols.

#define A_LD   520                       // padded row length (bf16), 1040 B stride
#define B_LD   136                       // padded row length (bf16), 272 B stride
#define A_BYTES (128 * A_LD * 2)         // 133120
#define B_BYTES (128 * B_LD * 2)         // 34816
#define SMEM_A_OFF 0
#define SMEM_B_OFF A_BYTES
#define SMEM_TOTAL (A_BYTES + 2 * B_BYTES)   // 202752

__device__ __forceinline__ void ldmatrix_x4(uint32_t& r0, uint32_t& r1,
                                            uint32_t& r2, uint32_t& r3, uint32_t addr) {
    asm volatile("ldmatrix.sync.aligned.m8n8.x4.shared.b16 {%0,%1,%2,%3}, [%4];"
                 : "=r"(r0), "=r"(r1), "=r"(r2), "=r"(r3) : "r"(addr));
}

__device__ __forceinline__ void mma_16816(float* c, uint32_t a0, uint32_t a1,
                                          uint32_t a2, uint32_t a3,
                                          uint32_t b0, uint32_t b1) {
    asm volatile(
        "mma.sync.aligned.m16n8k16.row.col.f32.bf16.bf16.f32 "
        "{%0,%1,%2,%3}, {%4,%5,%6,%7}, {%8,%9}, {%0,%1,%2,%3};"
        : "+f"(c[0]), "+f"(c[1]), "+f"(c[2]), "+f"(c[3])
        : "r"(a0), "r"(a1), "r"(a2), "r"(a3), "r"(b0), "r"(b1));
}

__device__ __forceinline__ void cp_async16(uint32_t dst, const void* src) {
    asm volatile("cp.async.cg.shared.global [%0], [%1], 16;"
                 :: "r"(dst), "l"(src) : "memory");
}
__device__ __forceinline__ void cp_async_commit() {
    asm volatile("cp.async.commit_group;" ::: "memory");
}
__device__ __forceinline__ void cp_async_wait0() {
    asm volatile("cp.async.wait_group 0;" ::: "memory");
}

__global__ void __launch_bounds__(256, 1) joint_kernel(float* __restrict__ out)
{
    extern __shared__ char smem[];
    const uint32_t smem_base = smem_to_u32(smem);
    const uint32_t A_base = smem_base + SMEM_A_OFF;

    const int tid  = threadIdx.x;
    const int wid  = tid >> 5;
    const int lane = tid & 31;
    const int cta  = blockIdx.x;             // b*T + t
    const int b    = cta >> 8;               // T = 256

    const int warp_m = wid >> 1;             // 0..3 -> rows warp_m*32
    const int warp_n = wid & 1;              // 0..1 -> cols warp_n*64

    // ---------- build A = bf16(relu(e+p)) into smem ----------
    {
        const int arow  = tid >> 1;
        const int acol0 = (tid & 1) * 256;
        const float* e_row = g_e + (size_t)cta * JH_SZ + acol0;
        const float* p_row = g_p + (size_t)(b * U_SZ + arow) * JH_SZ + acol0;
        char* adst = smem + SMEM_A_OFF + arow * (A_LD * 2) + acol0 * 2;
        #pragma unroll
        for (int i = 0; i < 32; ++i) {
            float4 ev0 = ((const float4*)e_row)[2 * i];
            float4 ev1 = ((const float4*)e_row)[2 * i + 1];
            float4 pv0 = ((const float4*)p_row)[2 * i];
            float4 pv1 = ((const float4*)p_row)[2 * i + 1];
            __nv_bfloat162 h0 = __floats2bfloat162_rn(fmaxf(ev0.x + pv0.x, 0.f),
                                                      fmaxf(ev0.y + pv0.y, 0.f));
            __nv_bfloat162 h1 = __floats2bfloat162_rn(fmaxf(ev0.z + pv0.z, 0.f),
                                                      fmaxf(ev0.w + pv0.w, 0.f));
            __nv_bfloat162 h2 = __floats2bfloat162_rn(fmaxf(ev1.x + pv1.x, 0.f),
                                                      fmaxf(ev1.y + pv1.y, 0.f));
            __nv_bfloat162 h3 = __floats2bfloat162_rn(fmaxf(ev1.z + pv1.z, 0.f),
                                                      fmaxf(ev1.w + pv1.w, 0.f));
            uint4 v;
            v.x = *reinterpret_cast<uint32_t*>(&h0);
            v.y = *reinterpret_cast<uint32_t*>(&h1);
            v.z = *reinterpret_cast<uint32_t*>(&h2);
            v.w = *reinterpret_cast<uint32_t*>(&h3);
            *reinterpret_cast<uint4*>(adst + i * 16) = v;
        }
    }

    // ---------- B chunk prefetch helper (chunk = nt*4 + kc) ----------
    auto issue_chunk = [&](int chunkIdx) {
        const int nt = chunkIdx >> 2;
        const int kc = chunkIdx & 3;
        const uint32_t dstb = smem_base + SMEM_B_OFF + (uint32_t)(chunkIdx & 1) * B_BYTES;
        const __nv_bfloat16* srcb = g_WT + (size_t)nt * 128 * JH_SZ + kc * 128;
        #pragma unroll
        for (int i = 0; i < 8; ++i) {
            int g  = tid + i * 256;          // 0..2047
            int n  = g >> 4;
            int kk = (g & 15) * 8;           // bf16 col within chunk
            cp_async16(dstb + n * (B_LD * 2) + kk * 2,
                       srcb + (size_t)n * JH_SZ + kk);
        }
        cp_async_commit();
    };

    issue_chunk(0);
    __syncthreads();   // A visible to all (ldmatrix later); also orders smem writes

    float c[2][8][4];

    for (int nt = 0; nt < NTILES; ++nt) {
        #pragma unroll
        for (int mi = 0; mi < 2; ++mi)
            #pragma unroll
            for (int ni = 0; ni < 8; ++ni)
                #pragma unroll
                for (int q = 0; q < 4; ++q) c[mi][ni][q] = 0.f;

        for (int kc = 0; kc < 4; ++kc) {
            const int chunk = nt * 4 + kc;
            cp_async_wait0();
            __syncthreads();
            if (chunk + 1 < NTILES * 4) issue_chunk(chunk + 1);

            const uint32_t Bb = smem_base + SMEM_B_OFF + (uint32_t)(chunk & 1) * B_BYTES;
            const int k_glob0 = kc * 128;

            #pragma unroll
            for (int ks = 0; ks < 8; ++ks) {
                const int kg = k_glob0 + ks * 16;         // A k index
                const int kl = ks * 16;                   // B k index within chunk

                // A fragments: rows warp_m*32 + mi*16
                uint32_t a[2][4];
                #pragma unroll
                for (int mi = 0; mi < 2; ++mi) {
                    int row = warp_m * 32 + mi * 16 + (lane & 15);
                    int kk  = kg + ((lane >> 4) & 1) * 8;
                    ldmatrix_x4(a[mi][0], a[mi][1], a[mi][2], a[mi][3],
                                A_base + row * (A_LD * 2) + kk * 2);
                }

                // B fragments: 4 groups of n16 -> 8 n8 frags
                uint32_t bfr[8][2];
                #pragma unroll
                for (int ng = 0; ng < 4; ++ng) {
                    int n  = warp_n * 64 + ng * 16 + ((lane >> 4) & 1) * 8 + (lane & 7);
                    int kk = kl + ((lane >> 3) & 1) * 8;
                    uint32_t r0, r1, r2, r3;
                    ldmatrix_x4(r0, r1, r2, r3, Bb + n * (B_LD * 2) + kk * 2);
                    bfr[ng * 2][0]     = r0; bfr[ng * 2][1]     = r1;
                    bfr[ng * 2 + 1][0] = r2; bfr[ng * 2 + 1][1] = r3;
                }

                #pragma unroll
                for (int mi = 0; mi < 2; ++mi)
                    #pragma unroll
                    for (int ni = 0; ni < 8; ++ni)
                        mma_16816(c[mi][ni], a[mi][0], a[mi][1], a[mi][2], a[mi][3],
                                  bfr[ni][0], bfr[ni][1]);
            }
        }

        // ---------- epilogue: bias + scalar stores (row stride 1025 floats is
        // only 4-byte aligned for odd rows -> vector stores would trap) ----------
        const int n_tile0 = nt * 128;
        #pragma unroll
        for (int mi = 0; mi < 2; ++mi) {
            int row_base = cta * 128 + warp_m * 32 + mi * 16 + (lane >> 2);
            #pragma unroll
            for (int rr = 0; rr < 2; ++rr) {
                float* rowptr = out + (size_t)(row_base + rr * 8) * NC_SZ;
                #pragma unroll
                for (int ni = 0; ni < 8; ++ni) {
                    int col = n_tile0 + warp_n * 64 + ni * 8 + (lane & 3) * 2;
                    float v0 = c[mi][ni][rr * 2]     + g_bias[col];
                    float v1 = c[mi][ni][rr * 2 + 1] + g_bias[col + 1];
                    if (col < NC_SZ)     rowptr[col]     = v0;
                    if (col + 1 < NC_SZ) rowptr[col + 1] = v1;
                }
            }
        }
    }
}

// ===================== in-place log_softmax over last dim (1025), warp per row =====================
__global__ void __launch_bounds__(256) lsm_kernel(float* __restrict__ out)
{
    const int wid  = threadIdx.x >> 5;
    const int lane = threadIdx.x & 31;
    const int row  = blockIdx.x * 8 + wid;          // 16384 * 8 = 131072 rows
    const size_t base = (size_t)row * NC_SZ;

    float v[33];
    #pragma unroll
    for (int k = 0; k < 32; ++k) v[k] = out[base + lane + k * 32];
    v[32] = (lane == 0) ? out[base + 1024] : -1e30f;

    float m = v[0];
    #pragma unroll
    for (int k = 1; k < 33; ++k) m = fmaxf(m, v[k]);
    #pragma unroll
    for (int off = 16; off > 0; off >>= 1)
        m = fmaxf(m, __shfl_xor_sync(0xffffffffu, m, off));

    float s = 0.f;
    #pragma unroll
    for (int k = 0; k < 33; ++k) s += __expf(v[k] - m);
    #pragma unroll
    for (int off = 16; off > 0; off >>= 1)
        s += __shfl_xor_sync(0xffffffffu, s, off);

    const float lse = m + __logf(s);

    #pragma unroll
    for (int k = 0; k < 32; ++k) out[base + lane + k * 32] = v[k] - lse;
    if (lane == 0) out[base + 1024] = v[32] - lse;
}

// ===================== launch =====================
extern "C" void kernel_launch(void* const* d_in, const int* in_sizes, int n_in,
                              void* d_out, int out_size)
{
    const float* enc    = (const float*)d_in[0];   // [B, EH, T]
    const float* dec    = (const float*)d_in[1];   // [B, PH, U]
    const float* W_enc  = (const float*)d_in[2];   // [EH, JH]
    const float* b_enc  = (const float*)d_in[3];   // [JH]
    const float* W_pred = (const float*)d_in[4];   // [PH, JH]
    const float* b_pred = (const float*)d_in[5];   // [JH]
    const float* W_out  = (const float*)d_in[6];   // [JH, NC]
    const float* b_out  = (const float*)d_in[7];   // [NC]
    float* out = (float*)d_out;

    (void)in_sizes; (void)n_in; (void)out_size;

    // projections: e (rows B*T=1024, K=512), p (rows B*U=512, K=320)
    proj_kernel<<<dim3(16, 8), 256>>>(enc, W_enc, b_enc, 0, EH_SZ, T_SZ);
    proj_kernel<<<dim3(8, 8), 256>>>(dec, W_pred, b_pred, 1, PH_SZ, U_SZ);

    // W_out^T (bf16, padded) + padded bias
    prep_wt_kernel<<<dim3(36, 16), dim3(32, 8)>>>(W_out, b_out);

    // joint logits (unconditional attribute set: no static guards allowed)
    cudaFuncSetAttribute(joint_kernel, cudaFuncAttributeMaxDynamicSharedMemorySize, SMEM_TOTAL);
    joint_kernel<<<B_SZ * T_SZ, 256, SMEM_TOTAL>>>(out);

    // in-place log_softmax
    lsm_kernel<<<16384, 256>>>(out);
}

// round 10
// speedup vs baseline: 1.4782x; 1.4782x over previous
#include <cuda_runtime.h>
#include <cuda_bf16.h>
#include <cstdint>

// ===================== problem constants =====================
#define B_SZ   4
#define T_SZ   256
#define U_SZ   128
#define EH_SZ  512
#define PH_SZ  320
#define JH_SZ  512
#define NC_SZ  1025
#define NPAD   1152           // 9 * 128
#define NTILES 9

// ===================== device scratch (statically declared; no allocs) =====================
__device__ float          g_e[B_SZ * T_SZ * JH_SZ];   // [B*T, JH] fp32 (2 MB)
__device__ float          g_p[B_SZ * U_SZ * JH_SZ];   // [B*U, JH] fp32 (1 MB)
__device__ __nv_bfloat16  g_WT[NPAD * JH_SZ];         // W_out^T bf16 [NPAD, JH] (1.18 MB)
__device__ float          g_bias[NPAD];               // b_out padded with 0

__device__ __forceinline__ uint32_t smem_to_u32(const void* smem_ptr) {
    uint32_t addr;
    asm("{ .reg .u64 tmp; cvta.to.shared.u64 tmp, %1; cvt.u32.u64 %0, tmp; }"
        : "=r"(addr) : "l"(smem_ptr));
    return addr;
}

// ===================== projection GEMM: out[b*R + r, j] = sum_h X[b,h,r]*W[h,j] + bias[j] =====================
__global__ void __launch_bounds__(256) proj_kernel(
    const float* __restrict__ X, const float* __restrict__ W,
    const float* __restrict__ bias, int which, int K, int R)
{
    float* out = which ? g_p : g_e;
    __shared__ float As[32][64];
    __shared__ float Bs[32][64];

    const int tid = threadIdx.x;
    const int tx = tid & 15, ty = tid >> 4;
    const int r0 = blockIdx.x * 64;
    const int j0 = blockIdx.y * 64;
    const int b  = r0 / R;
    const int t0 = r0 % R;
    const float* Xb = X + (size_t)b * K * R;

    float acc[4][4];
    #pragma unroll
    for (int i = 0; i < 4; ++i)
        #pragma unroll
        for (int j = 0; j < 4; ++j) acc[i][j] = 0.f;

    for (int k0 = 0; k0 < K; k0 += 32) {
        #pragma unroll
        for (int i = 0; i < 8; ++i) {
            int idx = tid + i * 256;
            int kk = idx >> 6, tt = idx & 63;
            As[kk][tt] = Xb[(size_t)(k0 + kk) * R + t0 + tt];
        }
        #pragma unroll
        for (int i = 0; i < 8; ++i) {
            int idx = tid + i * 256;
            int kk = idx >> 6, jj = idx & 63;
            Bs[kk][jj] = W[(size_t)(k0 + kk) * JH_SZ + j0 + jj];
        }
        __syncthreads();
        #pragma unroll
        for (int kk = 0; kk < 32; ++kk) {
            float a[4], bb[4];
            #pragma unroll
            for (int i = 0; i < 4; ++i) a[i]  = As[kk][ty * 4 + i];
            #pragma unroll
            for (int j = 0; j < 4; ++j) bb[j] = Bs[kk][tx * 4 + j];
            #pragma unroll
            for (int i = 0; i < 4; ++i)
                #pragma unroll
                for (int j = 0; j < 4; ++j) acc[i][j] += a[i] * bb[j];
        }
        __syncthreads();
    }

    #pragma unroll
    for (int i = 0; i < 4; ++i)
        #pragma unroll
        for (int j = 0; j < 4; ++j) {
            int jj = j0 + tx * 4 + j;
            out[(size_t)(r0 + ty * 4 + i) * JH_SZ + jj] = acc[i][j] + bias[jj];
        }
}

// ===================== W_out transpose + pad: g_WT[n,j] = bf16(W_out[j,n]); g_bias pad =====================
__global__ void prep_wt_kernel(const float* __restrict__ W_out, const float* __restrict__ b_out)
{
    __shared__ float tile[32][33];
    const int tx = threadIdx.x, ty = threadIdx.y;
    const int n0 = blockIdx.x * 32;     // 36 blocks -> 1152
    const int j0 = blockIdx.y * 32;     // 16 blocks -> 512

    #pragma unroll
    for (int k = 0; k < 4; ++k) {
        int j = j0 + ty + k * 8;
        int n = n0 + tx;
        tile[ty + k * 8][tx] = (n < NC_SZ) ? W_out[(size_t)j * NC_SZ + n] : 0.f;
    }
    __syncthreads();
    #pragma unroll
    for (int k = 0; k < 4; ++k) {
        int n = n0 + ty + k * 8;
        int j = j0 + tx;
        g_WT[(size_t)n * JH_SZ + j] = __float2bfloat16(tile[tx][ty + k * 8]);
    }
    if (blockIdx.y == 0 && ty == 0) {
        int n = n0 + tx;
        g_bias[n] = (n < NC_SZ) ? b_out[n] : 0.f;
    }
}

// ===================== joint kernel (mma.sync bf16), occupancy-2 version =====================
// CTA = 64 rows (half the u's of one (b,t)): A[64 x 512] bf16 in smem.
// Grid 2048 = (b,t) * 2 halves. 9 N-tiles of 128; B chunks [128n x 64k] cp.async
// double-buffered. Warps: 2M x 4N -> warp tile 32 rows x 32 cols (c = 32 regs).

#define A_LD   520                       // padded row (bf16): 1040 B stride
#define B_LD   72                        // padded row (bf16): 144 B stride
#define A_BYTES (64 * A_LD * 2)          // 66560
#define B_BYTES (128 * B_LD * 2)         // 18432
#define SMEM_A_OFF 0
#define SMEM_B_OFF A_BYTES
#define SMEM_TOTAL (A_BYTES + 2 * B_BYTES)   // 103424  -> 2 CTAs/SM
#define NKC    8                         // 64-wide k chunks per 512
#define NCHUNKS (NTILES * NKC)           // 72

__device__ __forceinline__ void ldmatrix_x4(uint32_t& r0, uint32_t& r1,
                                            uint32_t& r2, uint32_t& r3, uint32_t addr) {
    asm volatile("ldmatrix.sync.aligned.m8n8.x4.shared.b16 {%0,%1,%2,%3}, [%4];"
                 : "=r"(r0), "=r"(r1), "=r"(r2), "=r"(r3) : "r"(addr));
}

__device__ __forceinline__ void mma_16816(float* c, uint32_t a0, uint32_t a1,
                                          uint32_t a2, uint32_t a3,
                                          uint32_t b0, uint32_t b1) {
    asm volatile(
        "mma.sync.aligned.m16n8k16.row.col.f32.bf16.bf16.f32 "
        "{%0,%1,%2,%3}, {%4,%5,%6,%7}, {%8,%9}, {%0,%1,%2,%3};"
        : "+f"(c[0]), "+f"(c[1]), "+f"(c[2]), "+f"(c[3])
        : "r"(a0), "r"(a1), "r"(a2), "r"(a3), "r"(b0), "r"(b1));
}

__device__ __forceinline__ void cp_async16(uint32_t dst, const void* src) {
    asm volatile("cp.async.cg.shared.global [%0], [%1], 16;"
                 :: "r"(dst), "l"(src) : "memory");
}
__device__ __forceinline__ void cp_async_commit() {
    asm volatile("cp.async.commit_group;" ::: "memory");
}
__device__ __forceinline__ void cp_async_wait0() {
    asm volatile("cp.async.wait_group 0;" ::: "memory");
}

__global__ void __launch_bounds__(256, 2) joint_kernel(float* __restrict__ out)
{
    extern __shared__ char smem[];
    const uint32_t smem_base = smem_to_u32(smem);
    const uint32_t A_base = smem_base + SMEM_A_OFF;

    const int tid  = threadIdx.x;
    const int wid  = tid >> 5;
    const int lane = tid & 31;
    const int bt   = blockIdx.x >> 1;        // (b,t) index
    const int half = blockIdx.x & 1;         // which 64 u's
    const int b    = bt >> 8;                // T = 256

    const int warp_m = wid >> 2;             // 0..1 -> rows warp_m*32
    const int warp_n = wid & 3;              // 0..3 -> cols warp_n*32

    // ---------- build A = bf16(relu(e+p)) into smem: 64 rows x 512 ----------
    {
        const int arow  = tid >> 2;                  // 0..63
        const int acol0 = (tid & 3) * 128;           // 0,128,256,384
        const float* e_row = g_e + (size_t)bt * JH_SZ + acol0;
        const float* p_row = g_p + (size_t)(b * U_SZ + half * 64 + arow) * JH_SZ + acol0;
        char* adst = smem + SMEM_A_OFF + arow * (A_LD * 2) + acol0 * 2;
        #pragma unroll
        for (int i = 0; i < 16; ++i) {
            float4 ev0 = ((const float4*)e_row)[2 * i];
            float4 ev1 = ((const float4*)e_row)[2 * i + 1];
            float4 pv0 = ((const float4*)p_row)[2 * i];
            float4 pv1 = ((const float4*)p_row)[2 * i + 1];
            __nv_bfloat162 h0 = __floats2bfloat162_rn(fmaxf(ev0.x + pv0.x, 0.f),
                                                      fmaxf(ev0.y + pv0.y, 0.f));
            __nv_bfloat162 h1 = __floats2bfloat162_rn(fmaxf(ev0.z + pv0.z, 0.f),
                                                      fmaxf(ev0.w + pv0.w, 0.f));
            __nv_bfloat162 h2 = __floats2bfloat162_rn(fmaxf(ev1.x + pv1.x, 0.f),
                                                      fmaxf(ev1.y + pv1.y, 0.f));
            __nv_bfloat162 h3 = __floats2bfloat162_rn(fmaxf(ev1.z + pv1.z, 0.f),
                                                      fmaxf(ev1.w + pv1.w, 0.f));
            uint4 v;
            v.x = *reinterpret_cast<uint32_t*>(&h0);
            v.y = *reinterpret_cast<uint32_t*>(&h1);
            v.z = *reinterpret_cast<uint32_t*>(&h2);
            v.w = *reinterpret_cast<uint32_t*>(&h3);
            *reinterpret_cast<uint4*>(adst + i * 16) = v;
        }
    }

    // ---------- B chunk prefetch (chunk = nt*8 + kc): [128 n x 64 k] ----------
    auto issue_chunk = [&](int chunkIdx) {
        const int nt = chunkIdx >> 3;
        const int kc = chunkIdx & 7;
        const uint32_t dstb = smem_base + SMEM_B_OFF + (uint32_t)(chunkIdx & 1) * B_BYTES;
        const __nv_bfloat16* srcb = g_WT + (size_t)nt * 128 * JH_SZ + kc * 64;
        #pragma unroll
        for (int i = 0; i < 4; ++i) {
            int g  = tid + i * 256;          // 0..1023 16B granules
            int n  = g >> 3;                 // 8 granules per 64-k row
            int kk = (g & 7) * 8;            // bf16 col within chunk
            cp_async16(dstb + n * (B_LD * 2) + kk * 2,
                       srcb + (size_t)n * JH_SZ + kk);
        }
        cp_async_commit();
    };

    issue_chunk(0);
    __syncthreads();   // A visible to all warps

    float c[2][4][4];

    for (int nt = 0; nt < NTILES; ++nt) {
        #pragma unroll
        for (int mi = 0; mi < 2; ++mi)
            #pragma unroll
            for (int ni = 0; ni < 4; ++ni)
                #pragma unroll
                for (int q = 0; q < 4; ++q) c[mi][ni][q] = 0.f;

        for (int kc = 0; kc < NKC; ++kc) {
            const int chunk = nt * NKC + kc;
            cp_async_wait0();
            __syncthreads();
            if (chunk + 1 < NCHUNKS) issue_chunk(chunk + 1);

            const uint32_t Bb = smem_base + SMEM_B_OFF + (uint32_t)(chunk & 1) * B_BYTES;
            const int k_glob0 = kc * 64;

            #pragma unroll
            for (int ks = 0; ks < 4; ++ks) {
                const int kg = k_glob0 + ks * 16;         // A k index (0..511)
                const int kl = ks * 16;                   // B k index within chunk

                uint32_t a[2][4];
                #pragma unroll
                for (int mi = 0; mi < 2; ++mi) {
                    int row = warp_m * 32 + mi * 16 + (lane & 15);
                    int kk  = kg + ((lane >> 4) & 1) * 8;
                    ldmatrix_x4(a[mi][0], a[mi][1], a[mi][2], a[mi][3],
                                A_base + row * (A_LD * 2) + kk * 2);
                }

                uint32_t bfr[4][2];
                #pragma unroll
                for (int ng = 0; ng < 2; ++ng) {
                    int n  = warp_n * 32 + ng * 16 + ((lane >> 4) & 1) * 8 + (lane & 7);
                    int kk = kl + ((lane >> 3) & 1) * 8;
                    uint32_t r0, r1, r2, r3;
                    ldmatrix_x4(r0, r1, r2, r3, Bb + n * (B_LD * 2) + kk * 2);
                    bfr[ng * 2][0]     = r0; bfr[ng * 2][1]     = r1;
                    bfr[ng * 2 + 1][0] = r2; bfr[ng * 2 + 1][1] = r3;
                }

                #pragma unroll
                for (int mi = 0; mi < 2; ++mi)
                    #pragma unroll
                    for (int ni = 0; ni < 4; ++ni)
                        mma_16816(c[mi][ni], a[mi][0], a[mi][1], a[mi][2], a[mi][3],
                                  bfr[ni][0], bfr[ni][1]);
            }
        }

        // ---------- epilogue: bias + scalar stores (odd row stride: no vectors) ----------
        const int n_tile0 = nt * 128;
        #pragma unroll
        for (int mi = 0; mi < 2; ++mi) {
            int row_base = bt * 128 + half * 64 + warp_m * 32 + mi * 16 + (lane >> 2);
            #pragma unroll
            for (int rr = 0; rr < 2; ++rr) {
                float* rowptr = out + (size_t)(row_base + rr * 8) * NC_SZ;
                #pragma unroll
                for (int ni = 0; ni < 4; ++ni) {
                    int col = n_tile0 + warp_n * 32 + ni * 8 + (lane & 3) * 2;
                    float v0 = c[mi][ni][rr * 2]     + g_bias[col];
                    float v1 = c[mi][ni][rr * 2 + 1] + g_bias[col + 1];
                    if (col < NC_SZ)     rowptr[col]     = v0;
                    if (col + 1 < NC_SZ) rowptr[col + 1] = v1;
                }
            }
        }
    }
}

// ===================== in-place log_softmax over last dim (1025), warp per row =====================
__global__ void __launch_bounds__(256) lsm_kernel(float* __restrict__ out)
{
    const int wid  = threadIdx.x >> 5;
    const int lane = threadIdx.x & 31;
    const int row  = blockIdx.x * 8 + wid;          // 16384 * 8 = 131072 rows
    const size_t base = (size_t)row * NC_SZ;

    float v[33];
    #pragma unroll
    for (int k = 0; k < 32; ++k) v[k] = out[base + lane + k * 32];
    v[32] = (lane == 0) ? out[base + 1024] : -1e30f;

    float m = v[0];
    #pragma unroll
    for (int k = 1; k < 33; ++k) m = fmaxf(m, v[k]);
    #pragma unroll
    for (int off = 16; off > 0; off >>= 1)
        m = fmaxf(m, __shfl_xor_sync(0xffffffffu, m, off));

    float s = 0.f;
    #pragma unroll
    for (int k = 0; k < 33; ++k) s += __expf(v[k] - m);
    #pragma unroll
    for (int off = 16; off > 0; off >>= 1)
        s += __shfl_xor_sync(0xffffffffu, s, off);

    const float lse = m + __logf(s);

    #pragma unroll
    for (int k = 0; k < 32; ++k) out[base + lane + k * 32] = v[k] - lse;
    if (lane == 0) out[base + 1024] = v[32] - lse;
}

// ===================== launch =====================
extern "C" void kernel_launch(void* const* d_in, const int* in_sizes, int n_in,
                              void* d_out, int out_size)
{
    const float* enc    = (const float*)d_in[0];   // [B, EH, T]
    const float* dec    = (const float*)d_in[1];   // [B, PH, U]
    const float* W_enc  = (const float*)d_in[2];   // [EH, JH]
    const float* b_enc  = (const float*)d_in[3];   // [JH]
    const float* W_pred = (const float*)d_in[4];   // [PH, JH]
    const float* b_pred = (const float*)d_in[5];   // [JH]
    const float* W_out  = (const float*)d_in[6];   // [JH, NC]
    const float* b_out  = (const float*)d_in[7];   // [NC]
    float* out = (float*)d_out;

    (void)in_sizes; (void)n_in; (void)out_size;

    // projections: e (rows B*T=1024, K=512), p (rows B*U=512, K=320)
    proj_kernel<<<dim3(16, 8), 256>>>(enc, W_enc, b_enc, 0, EH_SZ, T_SZ);
    proj_kernel<<<dim3(8, 8), 256>>>(dec, W_pred, b_pred, 1, PH_SZ, U_SZ);

    // W_out^T (bf16, padded) + padded bias
    prep_wt_kernel<<<dim3(36, 16), dim3(32, 8)>>>(W_out, b_out);

    // joint logits
    cudaFuncSetAttribute(joint_kernel, cudaFuncAttributeMaxDynamicSharedMemorySize, SMEM_TOTAL);
    joint_kernel<<<B_SZ * T_SZ * 2, 256, SMEM_TOTAL>>>(out);

    // in-place log_softmax
    lsm_kernel<<<16384, 256>>>(out);
}